// round 1
// baseline (speedup 1.0000x reference)
#include <cuda_runtime.h>
#include <cstdint>
#include <cstddef>

typedef unsigned long long ull;

// ---------------------------------------------------------------------------
// f32x2 packed-math helpers (Blackwell sm_103a: fma.rn.f32x2 doubles fp32 rate)
// ---------------------------------------------------------------------------
__device__ __forceinline__ ull pack2(float lo, float hi) {
    ull r;
    asm("mov.b64 %0, {%1, %2};" : "=l"(r) : "f"(lo), "f"(hi));
    return r;
}
__device__ __forceinline__ void unpack2(ull v, float& lo, float& hi) {
    asm("mov.b64 {%0, %1}, %2;" : "=f"(lo), "=f"(hi) : "l"(v));
}
__device__ __forceinline__ ull fma2(ull a, ull b, ull c) {
    ull d;
    asm("fma.rn.f32x2 %0, %1, %2, %3;" : "=l"(d) : "l"(a), "l"(b), "l"(c));
    return d;
}
__device__ __forceinline__ ull add2(ull a, ull b) {
    ull d;
    asm("add.rn.f32x2 %0, %1, %2;" : "=l"(d) : "l"(a), "l"(b));
    return d;
}

// ---------------------------------------------------------------------------
// Problem constants
// ---------------------------------------------------------------------------
#define B_    4
#define CIN_  3
#define T_    32
#define H_    64
#define W_    64
#define COUT_ 64
#define NCH_  (4 * COUT_)   // 256 gate channels
#define HW_   (H_ * W_)     // 4096
#define KTAPS 54            // CIN*2*3*3

// Gate scratch: (B, 4*COUT, T, H, W) = 4*256*32*4096 floats = 512 MB
__device__ float g_E[(size_t)B_ * NCH_ * T_ * HW_];

// ---------------------------------------------------------------------------
// Conv kernel: 16x8 pixel tile per block, 128 threads, one pixel per thread.
// Channel-pair loop: weights paired {w[2p],w[2p+1]} in shared (LDS.128 reads
// fetch 2 taps), inputs duplicated {x,x} in 54 b64 registers.
// ---------------------------------------------------------------------------
#define TILE_H 16
#define TILE_W 8
#define CTHREADS 128
#define XS_ROWS 18
#define XS_COLS 10
#define XS_PLANE (XS_ROWS * XS_COLS)      // 180
#define SMEM_WS_ULL (128 * KTAPS)          // 6912 ull = 55296 B
#define SMEM_BYTES (SMEM_WS_ULL * 8 + 128 * 8 + 6 * XS_PLANE * 4)

__global__ void __launch_bounds__(CTHREADS)
conv_kernel(const float* __restrict__ X, const float* __restrict__ Wc,
            const float* __restrict__ bconv) {
    extern __shared__ __align__(16) char sm[];
    ull*   ws = (ull*)sm;                    // [128 pairs][54 taps]
    ull*   bs = ws + SMEM_WS_ULL;            // [128] bias pairs
    float* xs = (float*)(bs + 128);          // [6 planes][18][10]

    const int tid  = threadIdx.x;
    const int tile = blockIdx.x;             // 0..31
    const int t    = blockIdx.y;             // 0..31
    const int b    = blockIdx.z;             // 0..3
    const int h0   = (tile >> 3) * TILE_H;   // 0,16,32,48
    const int w0   = (tile & 7) * TILE_W;    // 0..56

    // Load weight pairs: ws[p*54+k] = {Wc[2p*54+k], Wc[(2p+1)*54+k]}
    for (int i = tid; i < SMEM_WS_ULL; i += CTHREADS) {
        int p = i / KTAPS;
        int k = i - p * KTAPS;
        ws[i] = pack2(Wc[(2 * p) * KTAPS + k], Wc[(2 * p + 1) * KTAPS + k]);
    }
    if (tid < 128) bs[tid] = pack2(bconv[2 * tid], bconv[2 * tid + 1]);

    // Load input halo tile: planes (ci,kd), rows/cols with -1 halo & zero pad.
    // Time slice index = t - 1 + kd (zero when negative: causal pad).
    for (int i = tid; i < 6 * XS_PLANE; i += CTHREADS) {
        int plane = i / XS_PLANE;
        int rem   = i - plane * XS_PLANE;
        int r     = rem / XS_COLS;
        int cc    = rem - r * XS_COLS;
        int ci    = plane >> 1;
        int kd    = plane & 1;
        int ts    = t - 1 + kd;
        int hh    = h0 - 1 + r;
        int wwp   = w0 - 1 + cc;
        float v = 0.f;
        if (ts >= 0 && hh >= 0 && hh < H_ && wwp >= 0 && wwp < W_)
            v = X[(((size_t)b * CIN_ + ci) * T_ + ts) * HW_ + hh * W_ + wwp];
        xs[i] = v;
    }
    __syncthreads();

    const int ty = tid >> 3;      // 0..15
    const int tx = tid & 7;       // 0..7

    // Duplicate this pixel's 54 taps into b64 registers {x,x}
    ull xd[KTAPS];
#pragma unroll
    for (int ci = 0; ci < 3; ci++)
#pragma unroll
        for (int kd = 0; kd < 2; kd++)
#pragma unroll
            for (int kh = 0; kh < 3; kh++)
#pragma unroll
                for (int kw = 0; kw < 3; kw++) {
                    float x = xs[(ci * 2 + kd) * XS_PLANE + (ty + kh) * XS_COLS + (tx + kw)];
                    xd[ci * 18 + kd * 9 + kh * 3 + kw] = pack2(x, x);
                }

    const size_t outb = ((size_t)b * NCH_ * T_) * HW_ + (size_t)t * HW_
                      + (size_t)(h0 + ty) * W_ + (w0 + tx);
    const ulonglong2* ws2 = (const ulonglong2*)ws;

    for (int p = 0; p < 128; p++) {
        ull a0 = bs[p];
        ull a1 = 0ull, a2 = 0ull, a3 = 0ull;
        const ulonglong2* wr = ws2 + p * 27;
#pragma unroll
        for (int kk = 0; kk < 27; kk++) {
            ulonglong2 w2 = wr[kk];
            if ((kk & 1) == 0) {
                a0 = fma2(xd[2 * kk],     w2.x, a0);
                a1 = fma2(xd[2 * kk + 1], w2.y, a1);
            } else {
                a2 = fma2(xd[2 * kk],     w2.x, a2);
                a3 = fma2(xd[2 * kk + 1], w2.y, a3);
            }
        }
        float slo, shi;
        unpack2(add2(add2(a0, a1), add2(a2, a3)), slo, shi);
        // oc stride in E = T*HW = 131072 floats
        g_E[outb + (size_t)(2 * p)     * (T_ * HW_)] = slo;
        g_E[outb + (size_t)(2 * p + 1) * (T_ * HW_)] = shi;
    }
}

// ---------------------------------------------------------------------------
// Recurrence kernel: elementwise peephole LSTM over T=32.
// One thread per (b, c, h, w). Coalesced: consecutive threads -> consecutive hw.
// ---------------------------------------------------------------------------
__device__ __forceinline__ float sigmoidf_(float x) {
    return 1.f / (1.f + __expf(-x));
}

__global__ void __launch_bounds__(256)
qrnn_kernel(const float* __restrict__ Wci, const float* __restrict__ Wcf,
            const float* __restrict__ Wco, float* __restrict__ out) {
    const int idx = blockIdx.x * 256 + threadIdx.x;   // 0 .. 1048575
    const int hw  = idx & (HW_ - 1);
    const int c   = (idx >> 12) & (COUT_ - 1);
    const int b   = idx >> 18;

    const float wci = Wci[(c << 12) + hw];
    const float wcf = Wcf[(c << 12) + hw];
    const float wco = Wco[(c << 12) + hw];

    // gate g lives at channel g*64+c -> base = ((b*4+g)*64+c)*T*HW + hw
    const size_t gstride = (size_t)COUT_ * T_ * HW_;  // 8388608
    const size_t gi = (((size_t)(b * 4) * COUT_ + c) * T_) * HW_ + hw;
    const size_t gf = gi + gstride;
    const size_t gg = gi + 2 * gstride;
    const size_t go = gi + 3 * gstride;
    const size_t ob = (((size_t)b * COUT_ + c) * T_) * HW_ + hw;

    float C = 0.f;
#pragma unroll 4
    for (int t = 0; t < T_; t++) {
        const size_t off = (size_t)t * HW_;
        float iv = g_E[gi + off];
        float fv = g_E[gf + off];
        float gv = g_E[gg + off];
        float ov = g_E[go + off];

        float ig = sigmoidf_(iv + wci * C);
        float fg = sigmoidf_(fv + wcf * C);
        float Cn = fg * C + ig * tanhf(gv);
        float og = sigmoidf_(ov + wco * Cn);
        out[ob + off] = og * tanhf(Cn);
        C = Cn;
    }
}

// ---------------------------------------------------------------------------
// kernel_launch
// ---------------------------------------------------------------------------
extern "C" void kernel_launch(void* const* d_in, const int* in_sizes, int n_in,
                              void* d_out, int out_size) {
    const float* X     = (const float*)d_in[0];
    const float* Wc    = (const float*)d_in[1];
    const float* bconv = (const float*)d_in[2];
    const float* Wci   = (const float*)d_in[3];
    const float* Wcf   = (const float*)d_in[4];
    const float* Wco   = (const float*)d_in[5];
    float* out = (float*)d_out;

    cudaFuncSetAttribute(conv_kernel, cudaFuncAttributeMaxDynamicSharedMemorySize,
                         SMEM_BYTES);

    dim3 cgrid(32, T_, B_);   // 32 tiles x 32 t x 4 b = 4096 blocks
    conv_kernel<<<cgrid, CTHREADS, SMEM_BYTES>>>(X, Wc, bconv);

    qrnn_kernel<<<(B_ * COUT_ * HW_) / 256, 256>>>(Wci, Wcf, Wco, out);
}

// round 2
// speedup vs baseline: 1.2354x; 1.2354x over previous
#include <cuda_runtime.h>
#include <cstdint>
#include <cstddef>

typedef unsigned long long ull;

// ---------------------------------------------------------------------------
// f32x2 packed-math helpers (Blackwell sm_103a: fma.rn.f32x2 doubles fp32 rate)
// ---------------------------------------------------------------------------
__device__ __forceinline__ ull pack2(float lo, float hi) {
    ull r;
    asm("mov.b64 %0, {%1, %2};" : "=l"(r) : "f"(lo), "f"(hi));
    return r;
}
__device__ __forceinline__ void unpack2(ull v, float& lo, float& hi) {
    asm("mov.b64 {%0, %1}, %2;" : "=f"(lo), "=f"(hi) : "l"(v));
}
__device__ __forceinline__ ull fma2(ull a, ull b, ull c) {
    ull d;
    asm("fma.rn.f32x2 %0, %1, %2, %3;" : "=l"(d) : "l"(a), "l"(b), "l"(c));
    return d;
}
__device__ __forceinline__ ull add2(ull a, ull b) {
    ull d;
    asm("add.rn.f32x2 %0, %1, %2;" : "=l"(d) : "l"(a), "l"(b));
    return d;
}
__device__ __forceinline__ float tanh_fast(float x) {
    float y;
    asm("tanh.approx.f32 %0, %1;" : "=f"(y) : "f"(x));
    return y;
}
__device__ __forceinline__ float sig_fast(float x) {
    return fmaf(0.5f, tanh_fast(0.5f * x), 0.5f);
}

// ---------------------------------------------------------------------------
// Problem constants
// ---------------------------------------------------------------------------
#define B_    4
#define CIN_  3
#define T_    32
#define H_    64
#define W_    64
#define COUT_ 64
#define NCH_  (4 * COUT_)   // 256 gate channels
#define HW_   (H_ * W_)     // 4096
#define KTAPS 54            // CIN*2*3*3

// Gate scratch: (B, 4*COUT, T, H, W) = 512 MB
__device__ float g_E[(size_t)B_ * NCH_ * T_ * HW_];
// Pre-packed weight pairs: [128 channel-pairs][54 taps] of {w[2p],w[2p+1]}
__device__ ull g_Wpk[128 * KTAPS];
__device__ ull g_Bpk[128];

// ---------------------------------------------------------------------------
// One-time (per launch) weight pre-pack
// ---------------------------------------------------------------------------
__global__ void __launch_bounds__(256)
pack_kernel(const float* __restrict__ Wc, const float* __restrict__ bconv) {
    int i = blockIdx.x * 256 + threadIdx.x;
    if (i < 128 * KTAPS) {
        int p = i / KTAPS;
        int k = i - p * KTAPS;
        g_Wpk[i] = pack2(Wc[(2 * p) * KTAPS + k], Wc[(2 * p + 1) * KTAPS + k]);
    }
    if (i < 128) g_Bpk[i] = pack2(bconv[2 * i], bconv[2 * i + 1]);
}

// ---------------------------------------------------------------------------
// Conv kernel: 16x8 pixel tile, 128 threads, one pixel per thread.
// Channel-pair loop: paired weights staged into shared from the pre-packed
// table (fast vector copy); inputs duplicated {x,x} in 54 b64 regs.
// ---------------------------------------------------------------------------
#define TILE_H 16
#define TILE_W 8
#define CTHREADS 128
#define XS_ROWS 18
#define XS_COLS 10
#define XS_PLANE (XS_ROWS * XS_COLS)       // 180
#define SMEM_WS_ULL (128 * KTAPS)           // 6912 ull = 55296 B
#define SMEM_BYTES (SMEM_WS_ULL * 8 + 128 * 8 + 6 * XS_PLANE * 4)

__global__ void __launch_bounds__(CTHREADS, 3)
conv_kernel(const float* __restrict__ X) {
    extern __shared__ __align__(16) char sm[];
    ull*   ws = (ull*)sm;                    // [128 pairs][54 taps]
    ull*   bs = ws + SMEM_WS_ULL;            // [128] bias pairs
    float* xs = (float*)(bs + 128);          // [6 planes][18][10]

    const int tid  = threadIdx.x;
    const int tile = blockIdx.x;             // 0..31
    const int t    = blockIdx.y;             // 0..31
    const int b    = blockIdx.z;             // 0..3
    const int h0   = (tile >> 3) * TILE_H;
    const int w0   = (tile & 7) * TILE_W;

    // Stage packed weights: straight 16B vector copy (3456 ulonglong2)
    {
        const ulonglong2* src = (const ulonglong2*)g_Wpk;
        ulonglong2* dst = (ulonglong2*)ws;
#pragma unroll 9
        for (int i = tid; i < SMEM_WS_ULL / 2; i += CTHREADS)
            dst[i] = src[i];
        if (tid < 128) bs[tid] = g_Bpk[tid];
    }

    // Load input halo tile: planes (ci,kd); time slice t-1+kd (causal zero pad)
    for (int i = tid; i < 6 * XS_PLANE; i += CTHREADS) {
        int plane = i / XS_PLANE;
        int rem   = i - plane * XS_PLANE;
        int r     = rem / XS_COLS;
        int cc    = rem - r * XS_COLS;
        int ci    = plane >> 1;
        int kd    = plane & 1;
        int ts    = t - 1 + kd;
        int hh    = h0 - 1 + r;
        int wwp   = w0 - 1 + cc;
        float v = 0.f;
        if (ts >= 0 && hh >= 0 && hh < H_ && wwp >= 0 && wwp < W_)
            v = X[(((size_t)b * CIN_ + ci) * T_ + ts) * HW_ + hh * W_ + wwp];
        xs[i] = v;
    }
    __syncthreads();

    const int ty = tid >> 3;
    const int tx = tid & 7;

    // Duplicate this pixel's 54 taps into b64 registers {x,x}
    ull xd[KTAPS];
#pragma unroll
    for (int ci = 0; ci < 3; ci++)
#pragma unroll
        for (int kd = 0; kd < 2; kd++)
#pragma unroll
            for (int kh = 0; kh < 3; kh++)
#pragma unroll
                for (int kw = 0; kw < 3; kw++) {
                    float x = xs[(ci * 2 + kd) * XS_PLANE + (ty + kh) * XS_COLS + (tx + kw)];
                    xd[ci * 18 + kd * 9 + kh * 3 + kw] = pack2(x, x);
                }

    const size_t outb = ((size_t)b * NCH_ * T_) * HW_ + (size_t)t * HW_
                      + (size_t)(h0 + ty) * W_ + (w0 + tx);
    const ulonglong2* ws2 = (const ulonglong2*)ws;

    for (int p = 0; p < 128; p++) {
        ull a0 = bs[p];
        ull a1 = 0ull, a2 = 0ull, a3 = 0ull;
        const ulonglong2* wr = ws2 + p * 27;
#pragma unroll
        for (int kk = 0; kk < 27; kk++) {
            ulonglong2 w2 = wr[kk];
            if ((kk & 1) == 0) {
                a0 = fma2(xd[2 * kk],     w2.x, a0);
                a1 = fma2(xd[2 * kk + 1], w2.y, a1);
            } else {
                a2 = fma2(xd[2 * kk],     w2.x, a2);
                a3 = fma2(xd[2 * kk + 1], w2.y, a3);
            }
        }
        float slo, shi;
        unpack2(add2(add2(a0, a1), add2(a2, a3)), slo, shi);
        g_E[outb + (size_t)(2 * p)     * (T_ * HW_)] = slo;
        g_E[outb + (size_t)(2 * p + 1) * (T_ * HW_)] = shi;
    }
}

// ---------------------------------------------------------------------------
// Recurrence kernel: elementwise peephole LSTM over T=32, float4 per thread.
// All activations via tanh.approx.f32 (1 MUFU each; no fp32 divide).
// ---------------------------------------------------------------------------
#define QTHREADS 256

__global__ void __launch_bounds__(QTHREADS)
qrnn_kernel(const float* __restrict__ Wci, const float* __restrict__ Wcf,
            const float* __restrict__ Wco, float* __restrict__ out) {
    const int idx = blockIdx.x * QTHREADS + threadIdx.x;   // 0 .. 262143
    const int q   = idx & 1023;             // float4 index within HW
    const int c   = (idx >> 10) & (COUT_ - 1);
    const int b   = idx >> 16;

    const int pw = (c << 10) + q;           // float4 index into (COUT,H,W)
    const float4 wci = ((const float4*)Wci)[pw];
    const float4 wcf = ((const float4*)Wcf)[pw];
    const float4 wco = ((const float4*)Wco)[pw];

    const size_t gstride4 = (size_t)COUT_ * T_ * (HW_ / 4);
    const size_t gi = (((size_t)(b * 4) * COUT_ + c) * T_) * (HW_ / 4) + q;
    const size_t ob = (((size_t)b * COUT_ + c) * T_) * (HW_ / 4) + q;
    const float4* E4 = (const float4*)g_E;
    float4* out4 = (float4*)out;

    float4 C = make_float4(0.f, 0.f, 0.f, 0.f);
#pragma unroll 4
    for (int t = 0; t < T_; t++) {
        const size_t off = (size_t)t * (HW_ / 4);
        float4 iv = E4[gi + off];
        float4 fv = E4[gi + gstride4 + off];
        float4 gv = E4[gi + 2 * gstride4 + off];
        float4 ov = E4[gi + 3 * gstride4 + off];

        float4 Hn;
        {
            float ig = sig_fast(iv.x + wci.x * C.x);
            float fg = sig_fast(fv.x + wcf.x * C.x);
            float Cn = fg * C.x + ig * tanh_fast(gv.x);
            float og = sig_fast(ov.x + wco.x * Cn);
            Hn.x = og * tanh_fast(Cn); C.x = Cn;
        }
        {
            float ig = sig_fast(iv.y + wci.y * C.y);
            float fg = sig_fast(fv.y + wcf.y * C.y);
            float Cn = fg * C.y + ig * tanh_fast(gv.y);
            float og = sig_fast(ov.y + wco.y * Cn);
            Hn.y = og * tanh_fast(Cn); C.y = Cn;
        }
        {
            float ig = sig_fast(iv.z + wci.z * C.z);
            float fg = sig_fast(fv.z + wcf.z * C.z);
            float Cn = fg * C.z + ig * tanh_fast(gv.z);
            float og = sig_fast(ov.z + wco.z * Cn);
            Hn.z = og * tanh_fast(Cn); C.z = Cn;
        }
        {
            float ig = sig_fast(iv.w + wci.w * C.w);
            float fg = sig_fast(fv.w + wcf.w * C.w);
            float Cn = fg * C.w + ig * tanh_fast(gv.w);
            float og = sig_fast(ov.w + wco.w * Cn);
            Hn.w = og * tanh_fast(Cn); C.w = Cn;
        }
        out4[ob + off] = Hn;
    }
}

// ---------------------------------------------------------------------------
// kernel_launch
// ---------------------------------------------------------------------------
extern "C" void kernel_launch(void* const* d_in, const int* in_sizes, int n_in,
                              void* d_out, int out_size) {
    const float* X     = (const float*)d_in[0];
    const float* Wc    = (const float*)d_in[1];
    const float* bconv = (const float*)d_in[2];
    const float* Wci   = (const float*)d_in[3];
    const float* Wcf   = (const float*)d_in[4];
    const float* Wco   = (const float*)d_in[5];
    float* out = (float*)d_out;

    cudaFuncSetAttribute(conv_kernel, cudaFuncAttributeMaxDynamicSharedMemorySize,
                         SMEM_BYTES);

    pack_kernel<<<27, 256>>>(Wc, bconv);

    dim3 cgrid(32, T_, B_);
    conv_kernel<<<cgrid, CTHREADS, SMEM_BYTES>>>(X);

    qrnn_kernel<<<(B_ * COUT_ * HW_ / 4) / QTHREADS, QTHREADS>>>(Wci, Wcf, Wco, out);
}